// round 9
// baseline (speedup 1.0000x reference)
#include <cuda_runtime.h>

// ---------------- problem constants ------------------------------------------
#define NDST0 25600
#define NDST1 5120
#define NDST2 1024
#define NTOT  (NDST0 + NDST1 + NDST2)
#define NE0   256000
#define NE1   51200
#define NE2   10240
#define NETOT (NE0 + NE1 + NE2)
#define DIN   128
#define DH    256
#define DOUT  64

// ---------------- device scratch (no allocations allowed) --------------------
__device__ float g_agg[NDST0 * DIN];      // gather output (reused per layer)
__device__ float g_h1[NDST0 * DH];        // layer-0 raw GEMM output (pre-BN)
__device__ float g_h2[NDST1 * DH];        // layer-1 raw GEMM output (pre-BN)
// [deg | cur | stats0 | stats1]; deg/cur re-zeroed by last kernel each replay,
// stats0/stats1 zeroed (ALL 512 floats) by gather0/gather1 (kernel-boundary ordered).
__device__ int   g_zero[2 * NTOT + 4 * DH];
__device__ int   g_off0[NDST0 + 1];
__device__ int   g_off1[NDST1 + 1];
__device__ int   g_off2[NDST2 + 1];
__device__ int   g_esrc0[NE0];
__device__ int   g_esrc1[NE1];
__device__ int   g_esrc2[NE2];

// ---------------- combined CSR build -----------------------------------------
__global__ void k_hist_all(const int* __restrict__ d0, const int* __restrict__ d1,
                           const int* __restrict__ d2, int* __restrict__ deg) {
    int e = blockIdx.x * blockDim.x + threadIdx.x;
    if (e < NE0)                 atomicAdd(&deg[d0[e]], 1);
    else if (e < NE0 + NE1)      atomicAdd(&deg[NDST0 + d1[e - NE0]], 1);
    else if (e < NETOT)          atomicAdd(&deg[NDST0 + NDST1 + d2[e - NE0 - NE1]], 1);
}

// per-thread contiguous chunk, int4-vectorized loads/stores
__global__ void k_scan3(const int* __restrict__ deg, int* __restrict__ off0,
                        int* __restrict__ off1, int* __restrict__ off2) {
    __shared__ int part[1024];
    int b = blockIdx.x, t = threadIdx.x;
    int n    = (b == 0) ? NDST0 : (b == 1) ? NDST1 : NDST2;
    int base = (b == 0) ? 0 : (b == 1) ? NDST0 : NDST0 + NDST1;
    int* off = (b == 0) ? off0 : (b == 1) ? off1 : off2;
    const int* d = deg + base;

    int chunk = (n + 1023) >> 10;
    chunk = (chunk + 3) & ~3;                      // round to 4 for int4
    int lo = min(t * chunk, n), hi = min(lo + chunk, n);

    int s = 0;
    int i = lo;
    for (; i + 4 <= hi; i += 4) {
        int4 v = *(const int4*)(d + i);
        s += v.x + v.y + v.z + v.w;
    }
    for (; i < hi; i++) s += d[i];
    part[t] = s;
    __syncthreads();
    for (int st = 1; st < 1024; st <<= 1) {
        int v = (t >= st) ? part[t - st] : 0;
        __syncthreads();
        part[t] += v;
        __syncthreads();
    }
    int run = t ? part[t - 1] : 0;
    i = lo;
    for (; i + 4 <= hi; i += 4) {
        int4 v = *(const int4*)(d + i);
        int4 o;
        o.x = run;           o.y = run + v.x;
        o.z = o.y + v.y;     o.w = o.z + v.z;
        run = o.w + v.w;
        *(int4*)(off + i) = o;
    }
    for (; i < hi; i++) { off[i] = run; run += d[i]; }
    if (t == 1023) off[n] = part[1023];
}

__global__ void k_bucket_all(const int* __restrict__ s0, const int* __restrict__ d0,
                             const int* __restrict__ s1, const int* __restrict__ d1,
                             const int* __restrict__ s2, const int* __restrict__ d2,
                             const int* __restrict__ off0, const int* __restrict__ off1,
                             const int* __restrict__ off2, int* __restrict__ cur,
                             int* __restrict__ e0, int* __restrict__ e1, int* __restrict__ e2) {
    int e = blockIdx.x * blockDim.x + threadIdx.x;
    if (e < NE0) {
        int d = d0[e];
        e0[off0[d] + atomicAdd(&cur[d], 1)] = s0[e];
    } else if (e < NE0 + NE1) {
        int i = e - NE0, d = d1[i];
        e1[off1[d] + atomicAdd(&cur[NDST0 + d], 1)] = s1[i];
    } else if (e < NETOT) {
        int i = e - NE0 - NE1, d = d2[i];
        e2[off2[d] + atomicAdd(&cur[NDST0 + NDST1 + d], 1)] = s2[i];
    }
}

// ---------------- gather mean (optionally fused BN+ReLU on inputs) ------------
// zstats: if non-null, block 0 zeroes ALL 512 floats (stats for the NEXT gemm).
template <int D, bool BN>
__global__ void k_gather(const float* __restrict__ x, const int* __restrict__ esrc,
                         const int* __restrict__ off, float* __restrict__ agg, int nDst,
                         const float* __restrict__ stats, const float* __restrict__ gamma,
                         const float* __restrict__ beta, float invM,
                         float* __restrict__ zstats) {
    constexpr int R = D / 128;
    __shared__ float saa[D], sbb[D];
    int lane = threadIdx.x & 31;
    if (zstats && blockIdx.x == 0) {
        int t = threadIdx.x;          // blockDim = 256; zero 2*256 = 512 floats
        zstats[t]       = 0.f;
        zstats[t + 256] = 0.f;
    }
    if (BN) {
        int t = threadIdx.x;
        if (t < D) {
            float m = stats[t] * invM;
            float v = stats[t + D] * invM - m * m;
            float a = gamma[t] * rsqrtf(v + 1e-5f);
            saa[t] = a;
            sbb[t] = beta[t] - m * a;
        }
        __syncthreads();
    }
    int w = (blockIdx.x * blockDim.x + threadIdx.x) >> 5;
    if (w >= nDst) return;

    float4 ca[R], cb[R];
    if (BN) {
#pragma unroll
        for (int r = 0; r < R; r++) {
            ca[r] = *(const float4*)&saa[4 * lane + 128 * r];
            cb[r] = *(const float4*)&sbb[4 * lane + 128 * r];
        }
    }

    int beg = off[w], end = off[w + 1];
    float4 acc[R];
#pragma unroll
    for (int r = 0; r < R; r++) acc[r] = make_float4(0.f, 0.f, 0.f, 0.f);

    int e = beg;
    if (R == 1) {
        // 4-edge unroll: 4 independent rows in flight for MLP
        for (; e + 3 < end; e += 4) {
            const float4* p0 = (const float4*)(x + (long)esrc[e] * D) + lane;
            const float4* p1 = (const float4*)(x + (long)esrc[e + 1] * D) + lane;
            const float4* p2 = (const float4*)(x + (long)esrc[e + 2] * D) + lane;
            const float4* p3 = (const float4*)(x + (long)esrc[e + 3] * D) + lane;
            float4 v0 = p0[0], v1 = p1[0], v2 = p2[0], v3 = p3[0];
            acc[0].x += (v0.x + v1.x) + (v2.x + v3.x);
            acc[0].y += (v0.y + v1.y) + (v2.y + v3.y);
            acc[0].z += (v0.z + v1.z) + (v2.z + v3.z);
            acc[0].w += (v0.w + v1.w) + (v2.w + v3.w);
        }
    }
    for (; e + 1 < end; e += 2) {
        const float4* p0 = (const float4*)(x + (long)esrc[e] * D) + lane;
        const float4* p1 = (const float4*)(x + (long)esrc[e + 1] * D) + lane;
        float4 v0[R], v1[R];
#pragma unroll
        for (int r = 0; r < R; r++) { v0[r] = p0[r * 32]; v1[r] = p1[r * 32]; }
#pragma unroll
        for (int r = 0; r < R; r++) {
            if (BN) {
                v0[r].x = fmaxf(fmaf(v0[r].x, ca[r].x, cb[r].x), 0.f);
                v0[r].y = fmaxf(fmaf(v0[r].y, ca[r].y, cb[r].y), 0.f);
                v0[r].z = fmaxf(fmaf(v0[r].z, ca[r].z, cb[r].z), 0.f);
                v0[r].w = fmaxf(fmaf(v0[r].w, ca[r].w, cb[r].w), 0.f);
                v1[r].x = fmaxf(fmaf(v1[r].x, ca[r].x, cb[r].x), 0.f);
                v1[r].y = fmaxf(fmaf(v1[r].y, ca[r].y, cb[r].y), 0.f);
                v1[r].z = fmaxf(fmaf(v1[r].z, ca[r].z, cb[r].z), 0.f);
                v1[r].w = fmaxf(fmaf(v1[r].w, ca[r].w, cb[r].w), 0.f);
            }
            acc[r].x += v0[r].x + v1[r].x;
            acc[r].y += v0[r].y + v1[r].y;
            acc[r].z += v0[r].z + v1[r].z;
            acc[r].w += v0[r].w + v1[r].w;
        }
    }
    if (e < end) {
        const float4* p0 = (const float4*)(x + (long)esrc[e] * D) + lane;
#pragma unroll
        for (int r = 0; r < R; r++) {
            float4 v = p0[r * 32];
            if (BN) {
                v.x = fmaxf(fmaf(v.x, ca[r].x, cb[r].x), 0.f);
                v.y = fmaxf(fmaf(v.y, ca[r].y, cb[r].y), 0.f);
                v.z = fmaxf(fmaf(v.z, ca[r].z, cb[r].z), 0.f);
                v.w = fmaxf(fmaf(v.w, ca[r].w, cb[r].w), 0.f);
            }
            acc[r].x += v.x; acc[r].y += v.y; acc[r].z += v.z; acc[r].w += v.w;
        }
    }
    int c = end - beg;
    float inv = 1.0f / (float)(c > 0 ? c : 1);
    float4* o = (float4*)(agg + (long)w * D) + lane;
#pragma unroll
    for (int r = 0; r < R; r++) {
        acc[r].x *= inv; acc[r].y *= inv; acc[r].z *= inv; acc[r].w *= inv;
        o[r * 32] = acc[r];
    }
}

// ---------------- tf32 helpers ------------------------------------------------
__device__ __forceinline__ float tf32r(float x) {
    unsigned u;
    asm("cvt.rna.tf32.f32 %0, %1;" : "=r"(u) : "f"(x));
    return __uint_as_float(u);
}

__device__ __forceinline__ void mma_tf32(float (&d)[4], const unsigned (&a)[4],
                                         const unsigned (&b)[2]) {
    asm volatile(
        "mma.sync.aligned.m16n8k8.row.col.f32.tf32.tf32.f32 "
        "{%0,%1,%2,%3}, {%4,%5,%6,%7}, {%8,%9}, {%0,%1,%2,%3};\n"
        : "+f"(d[0]), "+f"(d[1]), "+f"(d[2]), "+f"(d[3])
        : "r"(a[0]), "r"(a[1]), "r"(a[2]), "r"(a[3]), "r"(b[0]), "r"(b[1]));
}

// ---------------- tensor-core fused dual GEMM (double-buffered) ---------------
// C = tf32(A1)@tf32(B1) + bias + tf32(bnrelu?(A2))@tf32(B2)
// Block 64x128, 8 warps (2x4), warp tile 32x32, BK=16, ~100 regs (no spill @occ2).
#define TCBK 16
__global__ __launch_bounds__(256, 2)
void k_gemm_tc(const float* __restrict__ A1, const float* __restrict__ A2,
               const float* __restrict__ B1, const float* __restrict__ B2,
               const float* __restrict__ bias, float* __restrict__ C,
               int M, int K0, int N, float* __restrict__ stats,
               const float* __restrict__ bnst, const float* __restrict__ bng,
               const float* __restrict__ bnb, float bnInv) {
    constexpr int MT = 64, MF = 2;
    __shared__ float As[2][MT][20];
    __shared__ float Bs[2][TCBK][136];
    __shared__ float s_sum[128];
    __shared__ float s_sq[128];
    __shared__ float s_aa[256];
    __shared__ float s_bb[256];

    const int tid  = threadIdx.x;
    const int lane = tid & 31;
    const int warp = tid >> 5;
    const int mw = (warp & 1) * (MT / 2);
    const int nw = (warp >> 1) * 32;
    const int m0 = blockIdx.x * MT, n0 = blockIdx.y * 128;
    const int q = lane & 3, r = lane >> 2;

    const int ar = tid >> 2;          // A-load row (0..63), 4 floats/thread
    const int ak = (tid & 3) * 4;
    const int bk = tid >> 4;          // B-load k (0..15)
    const int bc = (tid & 15) * 8;    // B-load col base

    const bool hasBN = (bnst != nullptr);
    if (hasBN && tid < 256) {
        float m = bnst[tid] * bnInv;
        float v = bnst[tid + 256] * bnInv - m * m;
        float a = bng[tid] * rsqrtf(v + 1e-5f);
        s_aa[tid] = a;
        s_bb[tid] = bnb[tid] - m * a;
    }
    if (tid < 128) { s_sum[tid] = 0.f; s_sq[tid] = 0.f; }

    float acc[MF][4][4];
#pragma unroll
    for (int mf = 0; mf < MF; mf++)
#pragma unroll
        for (int nf = 0; nf < 4; nf++)
#pragma unroll
            for (int c = 0; c < 4; c++) acc[mf][nf][c] = 0.f;

    const int K2 = 2 * K0;

    auto ldTile = [&](int kb, float4& a0, float4& b0, float4& b1) {
        const float* A = (kb < K0) ? A1 : A2;
        const float* B = (kb < K0) ? B1 : B2;
        int ko = (kb < K0) ? kb : kb - K0;
        a0 = *(const float4*)(A + (long)(m0 + ar) * K0 + ko + ak);
        const float* bp = B + (long)(ko + bk) * N + n0 + bc;
        b0 = *(const float4*)bp;
        b1 = *(const float4*)(bp + 4);
    };

    auto stTile = [&](int kb, int p, float4 a0, float4 b0, float4 b1) {
        int ko = (kb < K0) ? kb : kb - K0;
        float av[4] = {a0.x, a0.y, a0.z, a0.w};
        if (hasBN && kb >= K0) {
            int c = ko + ak;
#pragma unroll
            for (int j = 0; j < 4; j++)
                av[j] = fmaxf(fmaf(av[j], s_aa[c + j], s_bb[c + j]), 0.f);
        }
        *(float4*)&As[p][ar][ak] =
            make_float4(tf32r(av[0]), tf32r(av[1]), tf32r(av[2]), tf32r(av[3]));
        *(float4*)&Bs[p][bk][bc] =
            make_float4(tf32r(b0.x), tf32r(b0.y), tf32r(b0.z), tf32r(b0.w));
        *(float4*)&Bs[p][bk][bc + 4] =
            make_float4(tf32r(b1.x), tf32r(b1.y), tf32r(b1.z), tf32r(b1.w));
    };

    // prologue
    float4 pa0, pb0, pb1;
    ldTile(0, pa0, pb0, pb1);
    __syncthreads();                 // BN coeffs + s_sum init visible
    stTile(0, 0, pa0, pb0, pb1);
    __syncthreads();

    int p = 0;
    for (int kb = 0; kb < K2; kb += TCBK) {
        int nx = kb + TCBK;
        float4 na0, nb0, nb1;
        if (nx < K2) ldTile(nx, na0, nb0, nb1);

#pragma unroll
        for (int ks = 0; ks < TCBK; ks += 8) {
            unsigned a[MF][4], b[4][2];
#pragma unroll
            for (int mf = 0; mf < MF; mf++) {
                int m = mw + mf * 16 + r;
                a[mf][0] = __float_as_uint(As[p][m][ks + q]);
                a[mf][1] = __float_as_uint(As[p][m + 8][ks + q]);
                a[mf][2] = __float_as_uint(As[p][m][ks + q + 4]);
                a[mf][3] = __float_as_uint(As[p][m + 8][ks + q + 4]);
            }
#pragma unroll
            for (int nf = 0; nf < 4; nf++) {
                int n = nw + nf * 8 + r;
                b[nf][0] = __float_as_uint(Bs[p][ks + q][n]);
                b[nf][1] = __float_as_uint(Bs[p][ks + q + 4][n]);
            }
#pragma unroll
            for (int mf = 0; mf < MF; mf++)
#pragma unroll
                for (int nf = 0; nf < 4; nf++)
                    mma_tf32(acc[mf][nf], a[mf], b[nf]);
        }

        if (nx < K2) stTile(nx, p ^ 1, na0, nb0, nb1);
        __syncthreads();
        p ^= 1;
    }

    float bs0[4], bs1[4];
#pragma unroll
    for (int nf = 0; nf < 4; nf++) {
        int c = n0 + nw + nf * 8 + 2 * q;
        bs0[nf] = bias[c];
        bs1[nf] = bias[c + 1];
    }

    float csum0[4] = {}, csum1[4] = {}, csq0[4] = {}, csq1[4] = {};
#pragma unroll
    for (int mf = 0; mf < MF; mf++) {
        int row0 = m0 + mw + mf * 16 + r;
#pragma unroll
        for (int nf = 0; nf < 4; nf++) {
            int col = n0 + nw + nf * 8 + 2 * q;
            float v0 = acc[mf][nf][0] + bs0[nf];
            float v1 = acc[mf][nf][1] + bs1[nf];
            float v2 = acc[mf][nf][2] + bs0[nf];
            float v3 = acc[mf][nf][3] + bs1[nf];
            *(float2*)(C + (long)row0 * N + col)       = make_float2(v0, v1);
            *(float2*)(C + (long)(row0 + 8) * N + col) = make_float2(v2, v3);
            csum0[nf] += v0 + v2;
            csum1[nf] += v1 + v3;
            csq0[nf]  += v0 * v0 + v2 * v2;
            csq1[nf]  += v1 * v1 + v3 * v3;
        }
    }

    if (stats) {
#pragma unroll
        for (int nf = 0; nf < 4; nf++) {
            int cl = nw + nf * 8 + 2 * q;
            atomicAdd(&s_sum[cl],     csum0[nf]);
            atomicAdd(&s_sum[cl + 1], csum1[nf]);
            atomicAdd(&s_sq[cl],      csq0[nf]);
            atomicAdd(&s_sq[cl + 1],  csq1[nf]);
        }
        __syncthreads();
        if (tid < 128) {
            atomicAdd(&stats[n0 + tid],     s_sum[tid]);
            atomicAdd(&stats[N + n0 + tid], s_sq[tid]);
        }
    }
}

// ---------------- TC 64x64 dual GEMM for the final layer (BN on A2) -----------
// 128 threads (4 warps, 2x2), warp tile 32x32, BK=16, double-buffered.
// Epilogue: re-zeroes deg/cur (g_zero[0 .. 2*NTOT)) for the next graph replay.
__global__ __launch_bounds__(128, 4)
void k_gemm_tc64(const float* __restrict__ A1, const float* __restrict__ A2,
                 const float* __restrict__ B1, const float* __restrict__ B2,
                 const float* __restrict__ bias, float* __restrict__ C,
                 int M, int K0, int N,
                 const float* __restrict__ bnst, const float* __restrict__ bng,
                 const float* __restrict__ bnb, float bnInv,
                 int* __restrict__ zclean) {
    __shared__ float As[2][64][20];
    __shared__ float Bs[2][TCBK][72];
    __shared__ float s_aa[256];
    __shared__ float s_bb[256];

    const int tid  = threadIdx.x;
    const int lane = tid & 31;
    const int warp = tid >> 5;
    const int mw = (warp & 1) * 32;
    const int nw = (warp >> 1) * 32;
    const int m0 = blockIdx.x * 64;   // N fits one tile (grid.y == 1)
    const int q = lane & 3, r = lane >> 2;

    const int ar = tid >> 1;          // A row (0..63), 8 floats/thread
    const int ak = (tid & 1) * 8;
    const int bk = tid >> 3;          // B k (0..15), 8 floats/thread
    const int bc = (tid & 7) * 8;

    for (int t = tid; t < 256; t += 128) {
        float m = bnst[t] * bnInv;
        float v = bnst[t + 256] * bnInv - m * m;
        float a = bng[t] * rsqrtf(v + 1e-5f);
        s_aa[t] = a;
        s_bb[t] = bnb[t] - m * a;
    }

    float acc[2][4][4];
#pragma unroll
    for (int mf = 0; mf < 2; mf++)
#pragma unroll
        for (int nf = 0; nf < 4; nf++)
#pragma unroll
            for (int c = 0; c < 4; c++) acc[mf][nf][c] = 0.f;

    const int K2 = 2 * K0;

    auto ldTile = [&](int kb, float4& a0, float4& a1, float4& b0, float4& b1) {
        const float* A = (kb < K0) ? A1 : A2;
        const float* B = (kb < K0) ? B1 : B2;
        int ko = (kb < K0) ? kb : kb - K0;
        const float* ap = A + (long)(m0 + ar) * K0 + ko + ak;
        a0 = *(const float4*)ap;
        a1 = *(const float4*)(ap + 4);
        const float* bp = B + (long)(ko + bk) * N + bc;
        b0 = *(const float4*)bp;
        b1 = *(const float4*)(bp + 4);
    };

    auto stTile = [&](int kb, int p, float4 a0, float4 a1, float4 b0, float4 b1) {
        int ko = (kb < K0) ? kb : kb - K0;
        float av[8] = {a0.x, a0.y, a0.z, a0.w, a1.x, a1.y, a1.z, a1.w};
        if (kb >= K0) {
            int c = ko + ak;
#pragma unroll
            for (int j = 0; j < 8; j++)
                av[j] = fmaxf(fmaf(av[j], s_aa[c + j], s_bb[c + j]), 0.f);
        }
        *(float4*)&As[p][ar][ak] =
            make_float4(tf32r(av[0]), tf32r(av[1]), tf32r(av[2]), tf32r(av[3]));
        *(float4*)&As[p][ar][ak + 4] =
            make_float4(tf32r(av[4]), tf32r(av[5]), tf32r(av[6]), tf32r(av[7]));
        *(float4*)&Bs[p][bk][bc] =
            make_float4(tf32r(b0.x), tf32r(b0.y), tf32r(b0.z), tf32r(b0.w));
        *(float4*)&Bs[p][bk][bc + 4] =
            make_float4(tf32r(b1.x), tf32r(b1.y), tf32r(b1.z), tf32r(b1.w));
    };

    float4 pa0, pa1, pb0, pb1;
    ldTile(0, pa0, pa1, pb0, pb1);
    __syncthreads();                 // s_aa/s_bb visible
    stTile(0, 0, pa0, pa1, pb0, pb1);
    __syncthreads();

    int p = 0;
    for (int kb = 0; kb < K2; kb += TCBK) {
        int nx = kb + TCBK;
        float4 na0, na1, nb0, nb1;
        if (nx < K2) ldTile(nx, na0, na1, nb0, nb1);

#pragma unroll
        for (int ks = 0; ks < TCBK; ks += 8) {
            unsigned a[2][4], b[4][2];
#pragma unroll
            for (int mf = 0; mf < 2; mf++) {
                int m = mw + mf * 16 + r;
                a[mf][0] = __float_as_uint(As[p][m][ks + q]);
                a[mf][1] = __float_as_uint(As[p][m + 8][ks + q]);
                a[mf][2] = __float_as_uint(As[p][m][ks + q + 4]);
                a[mf][3] = __float_as_uint(As[p][m + 8][ks + q + 4]);
            }
#pragma unroll
            for (int nf = 0; nf < 4; nf++) {
                int n = nw + nf * 8 + r;
                b[nf][0] = __float_as_uint(Bs[p][ks + q][n]);
                b[nf][1] = __float_as_uint(Bs[p][ks + q + 4][n]);
            }
#pragma unroll
            for (int mf = 0; mf < 2; mf++)
#pragma unroll
                for (int nf = 0; nf < 4; nf++)
                    mma_tf32(acc[mf][nf], a[mf], b[nf]);
        }

        if (nx < K2) stTile(nx, p ^ 1, na0, na1, nb0, nb1);
        __syncthreads();
        p ^= 1;
    }

    float bs0[4], bs1[4];
#pragma unroll
    for (int nf = 0; nf < 4; nf++) {
        int c = nw + nf * 8 + 2 * q;
        bs0[nf] = bias[c];
        bs1[nf] = bias[c + 1];
    }

#pragma unroll
    for (int mf = 0; mf < 2; mf++) {
        int row0 = m0 + mw + mf * 16 + r;
#pragma unroll
        for (int nf = 0; nf < 4; nf++) {
            int col = nw + nf * 8 + 2 * q;
            *(float2*)(C + (long)row0 * N + col) =
                make_float2(acc[mf][nf][0] + bs0[nf], acc[mf][nf][1] + bs1[nf]);
            *(float2*)(C + (long)(row0 + 8) * N + col) =
                make_float2(acc[mf][nf][2] + bs0[nf], acc[mf][nf][3] + bs1[nf]);
        }
    }

    // re-zero deg/cur for the next replay (nothing reads them after bucket)
    {
        int4* z4 = (int4*)zclean;
        int n4 = (2 * NTOT) / 4;
        int stride = gridDim.x * blockDim.x;
        for (int i = blockIdx.x * blockDim.x + tid; i < n4; i += stride)
            z4[i] = make_int4(0, 0, 0, 0);
    }
}

// ---------------- launch ------------------------------------------------------
extern "C" void kernel_launch(void* const* d_in, const int* in_sizes, int n_in,
                              void* d_out, int out_size) {
    const float* x      = (const float*)d_in[0];
    const float* Wl0    = (const float*)d_in[1];
    const float* bl0    = (const float*)d_in[2];
    const float* Wr0    = (const float*)d_in[3];
    const float* Wl1    = (const float*)d_in[4];
    const float* bl1    = (const float*)d_in[5];
    const float* Wr1    = (const float*)d_in[6];
    const float* Wl2    = (const float*)d_in[7];
    const float* bl2    = (const float*)d_in[8];
    const float* Wr2    = (const float*)d_in[9];
    const float* gamma0 = (const float*)d_in[10];
    const float* beta0  = (const float*)d_in[11];
    const float* gamma1 = (const float*)d_in[12];
    const float* beta1  = (const float*)d_in[13];
    const int* src0 = (const int*)d_in[14];
    const int* dst0 = (const int*)d_in[15];
    const int* src1 = (const int*)d_in[16];
    const int* dst1 = (const int*)d_in[17];
    const int* src2 = (const int*)d_in[18];
    const int* dst2 = (const int*)d_in[19];
    float* out = (float*)d_out;

    float *agg, *h1, *h2;
    int *zero, *off0, *off1, *off2, *e0, *e1, *e2;
    cudaGetSymbolAddress((void**)&agg, g_agg);
    cudaGetSymbolAddress((void**)&h1, g_h1);
    cudaGetSymbolAddress((void**)&h2, g_h2);
    cudaGetSymbolAddress((void**)&zero, g_zero);
    cudaGetSymbolAddress((void**)&off0, g_off0);
    cudaGetSymbolAddress((void**)&off1, g_off1);
    cudaGetSymbolAddress((void**)&off2, g_off2);
    cudaGetSymbolAddress((void**)&e0, g_esrc0);
    cudaGetSymbolAddress((void**)&e1, g_esrc1);
    cudaGetSymbolAddress((void**)&e2, g_esrc2);

    int* deg = zero;
    int* cur = zero + NTOT;
    float* stats0 = (float*)(zero + 2 * NTOT);
    float* stats1 = stats0 + 2 * DH;

    // --- combined CSR build (deg/cur pre-zeroed by previous replay / loader) ---
    k_hist_all<<<(NETOT + 255) / 256, 256>>>(dst0, dst1, dst2, deg);
    k_scan3<<<3, 1024>>>(deg, off0, off1, off2);
    k_bucket_all<<<(NETOT + 255) / 256, 256>>>(src0, dst0, src1, dst1, src2, dst2,
                                               off0, off1, off2, cur, e0, e1, e2);

    // --- layer 0: IN=128 -> H=256, M = 25600 (gather0 zeroes stats0) ---
    k_gather<DIN, false><<<NDST0 * 32 / 256, 256>>>(x, e0, off0, agg, NDST0,
                                                    nullptr, nullptr, nullptr, 0.f,
                                                    stats0);
    {
        dim3 g(NDST0 / 64, DH / 128);
        k_gemm_tc<<<g, 256>>>(agg, x, Wl0, Wr0, bl0, h1, NDST0, DIN, DH, stats0,
                              nullptr, nullptr, nullptr, 0.f);
    }

    // --- layer 1: H=256 -> H=256, M = 5120 (BN0 fused; gather1 zeroes stats1) ---
    k_gather<DH, true><<<NDST1 * 32 / 256, 256>>>(h1, e1, off1, agg, NDST1,
                                                  stats0, gamma0, beta0, 1.0f / NDST0,
                                                  stats1);
    {
        dim3 g(NDST1 / 64, DH / 128);
        k_gemm_tc<<<g, 256>>>(agg, h1, Wl1, Wr1, bl1, h2, NDST1, DH, DH, stats1,
                              stats0, gamma0, beta0, 1.0f / NDST0);
    }

    // --- layer 2: H=256 -> OUT=64, M = 1024 (BN1 fused; TC; cleanup) ---
    k_gather<DH, true><<<NDST2 * 32 / 256, 256>>>(h2, e2, off2, agg, NDST2,
                                                  stats1, gamma1, beta1, 1.0f / NDST1,
                                                  nullptr);
    {
        dim3 g(NDST2 / 64, 1);
        k_gemm_tc64<<<g, 128>>>(agg, h2, Wl2, Wr2, bl2, out, NDST2, DH, DOUT,
                                stats1, gamma1, beta1, 1.0f / NDST1, zero);
    }
}